// round 9
// baseline (speedup 1.0000x reference)
#include <cuda_runtime.h>
#include <cstdint>

#define B_    8
#define CIN   32
#define COUT  32
#define H_    96
#define W_    96
#define K_    5

#define TILE_X 32
#define TILE_Y 16
#define CCHUNK 4

#define SCALE_F   2048.0f
#define INV_SCALE (1.0f / 2048.0f)
#define NEG_PACK  0x8AD08AD0u   // (-30000, -30000) as s16x2
#define NEG_S16   ((int16_t)-30000)

#define NW_ELEMS  ((COUT / 8) * CIN * K_ * K_ * 8)   // 25600
#define NW_BLOCKS ((NW_ELEMS + 255) / 256)           // 100

// Padded s16x2 f, two phase-shifted images. Word w of a row:
//   E: covers gx = (2w-2, 2w-1)      O: covers gx = (2w-1, 2w)
// row r <-> gy = r-2. Borders = NEG. 6.55 MB each.
__device__ uint32_t g_fpadE[B_][CIN][100][64];
__device__ uint32_t g_fpadO[B_][CIN][100][64];
// Pre-transposed duplicated weights: [o_group of 8][c][ij][o_local], (w,w) s16x2.
__device__ uint32_t g_w[COUT / 8][CIN][K_ * K_][8];

__device__ __forceinline__ uint32_t pack_s16x2(int a, int b) {
    return (uint32_t)(uint16_t)a | ((uint32_t)(uint16_t)b << 16);
}
__device__ __forceinline__ void cp16(uint32_t dst, const void* src) {
    asm volatile("cp.async.ca.shared.global [%0], [%1], 16;" :: "r"(dst), "l"(src));
}
__device__ __forceinline__ void cp8(uint32_t dst, const void* src) {
    asm volatile("cp.async.ca.shared.global [%0], [%1], 8;" :: "r"(dst), "l"(src));
}
__device__ __forceinline__ void cp4(uint32_t dst, const void* src) {
    asm volatile("cp.async.ca.shared.global [%0], [%1], 4;" :: "r"(dst), "l"(src));
}

// ---- Fused prep: blocks 0..1023 convert f into BOTH phase images
//      (quarter-plane each); blocks 1024..1123 handle the 25600 weight entries.
__global__ __launch_bounds__(256) void prep_kernel(const float* __restrict__ f,
                                                   const float* __restrict__ h)
{
    const int bx  = blockIdx.x;
    const int tid = threadIdx.x;

    if (bx < 1024) {
        const int bc = bx >> 2;            // b*32 + c
        const int q  = bx & 3;             // quarter of the 6400-word plane
        const float* fp = f + (size_t)bc * (H_ * W_);
        uint32_t* dstE = &g_fpadE[0][0][0][0] + (size_t)bc * 6400;
        uint32_t* dstO = &g_fpadO[0][0][0][0] + (size_t)bc * 6400;
        #pragma unroll
        for (int k = 0; k < 7; k++) {
            const int wi = q * 1600 + tid + k * 256;
            if (wi < (q + 1) * 1600) {
                const int ry = wi >> 6;
                const int cw = wi & 63;
                uint32_t ve = NEG_PACK, vo = NEG_PACK;
                if (ry >= 2 && ry < 98) {
                    const float* row = fp + (ry - 2) * W_;
                    int lo = NEG_S16, hi = NEG_S16;
                    // even image: gx = 2cw-2, 2cw-1
                    if (cw >= 1 && cw <= 48) {
                        lo = __float2int_rn(row[2 * cw - 2] * SCALE_F);
                        hi = __float2int_rn(row[2 * cw - 1] * SCALE_F);
                        ve = pack_s16x2(lo, hi);
                    }
                    // odd image: gx = 2cw-1, 2cw
                    lo = NEG_S16; hi = NEG_S16;
                    if (cw >= 1 && cw <= 48) lo = __float2int_rn(row[2 * cw - 1] * SCALE_F);
                    if (cw < 48)             hi = __float2int_rn(row[2 * cw] * SCALE_F);
                    vo = pack_s16x2(lo, hi);
                }
                dstE[wi] = ve;
                dstO[wi] = vo;
            }
        }
    } else {
        const int idx = (bx - 1024) * 256 + tid;
        if (idx < NW_ELEMS) {
            const int og  = idx / (CIN * K_ * K_ * 8);
            const int rem = idx % (CIN * K_ * K_ * 8);
            const int c   = rem / (K_ * K_ * 8);
            const int r2  = rem % (K_ * K_ * 8);
            const int ij  = r2 >> 3;
            const int ol  = r2 & 7;
            const float wv =
                h[(size_t)(og * 8 + ol) * (CIN * K_ * K_) + c * (K_ * K_) + ij];
            const int wq = __float2int_rn(wv * SCALE_F);
            g_w[og][c][ij][ol] = pack_s16x2(wq, wq);
        }
    }
}

// ---- Main kernel ----
// 128 threads: xg = tid&3 (4 groups of 8 px), tg = (tid>>2)&1 (o half),
// ty = tid>>3 (16 rows). Each thread: 8 px x 4 o = 32 outputs.
// Block: 8 o x 16 y x 32 x. Grid (3, 6, B*4) = 576 (all co-resident).
__global__ __launch_bounds__(128) void dilate2d_dpx_kernel(float* __restrict__ out)
{
    __shared__ __align__(16) uint32_t sw[CIN][K_ * K_][8];            // 25.6 KB
    __shared__ __align__(16) uint32_t sfe[2][CCHUNK][TILE_Y + 4][20]; // 12.8 KB
    __shared__ __align__(16) uint32_t sfo[2][CCHUNK][TILE_Y + 4][20]; // 12.8 KB

    const int tid = threadIdx.x;
    const int xg  = tid & 3;
    const int tg  = (tid >> 2) & 1;
    const int ty  = tid >> 3;

    const int bz = blockIdx.z;
    const int b  = bz >> 2;
    const int og = bz & 3;
    const int x0h = blockIdx.x * (TILE_X / 2);
    const int y0  = blockIdx.y * TILE_Y;

    // Staging role: 80 threads own one (cc, row) each.
    const bool stager = tid < CCHUNK * (TILE_Y + 4);
    const int scc = tid / (TILE_Y + 4);
    const int sr  = tid % (TILE_Y + 4);

    // Issue cp.async for one chunk into buffer s (10 ops per stager).
    auto stage = [&](int c0s, int s) {
        if (!stager || c0s >= CIN) return;
        const uint32_t* gE = &g_fpadE[b][c0s + scc][y0 + sr][x0h];
        const uint32_t* gO = &g_fpadO[b][c0s + scc][y0 + sr][x0h];
        const uint32_t de = (uint32_t)__cvta_generic_to_shared(&sfe[s][scc][sr][0]);
        const uint32_t dq = (uint32_t)__cvta_generic_to_shared(&sfo[s][scc][sr][0]);
        #pragma unroll
        for (int k = 0; k < 4; k++) {
            cp16(de + 16 * k, gE + 4 * k);
            cp16(dq + 16 * k, gO + 4 * k);
        }
        cp8(de + 64, gE + 16);   // even words 16,17
        cp4(dq + 64, gO + 16);   // odd word 16
    };

    // Kick chunk 0 immediately (overlaps with weight staging below).
    stage(0, 0);
    asm volatile("cp.async.commit_group;" ::: "memory");

    // Weights: vector copy of this o-group's pre-transposed block.
    {
        const uint4* src = reinterpret_cast<const uint4*>(&g_w[og][0][0][0]);
        uint4* dst = reinterpret_cast<uint4*>(&sw[0][0][0]);
        #pragma unroll
        for (int k = 0; k < 13; k++) {
            const int e = tid + k * 128;
            if (e < CIN * K_ * K_ * 2) dst[e] = src[e];
        }
    }

    uint32_t acc[4][4];
    #pragma unroll
    for (int oo = 0; oo < 4; oo++)
        #pragma unroll
        for (int p = 0; p < 4; p++)
            acc[oo][p] = NEG_PACK;

    #pragma unroll 1
    for (int n = 0; n < CIN / CCHUNK; n++) {
        const int c0 = n * CCHUNK;
        const int s  = n & 1;

        // Chunk n's cp.async group is the only outstanding one here.
        asm volatile("cp.async.wait_group 0;" ::: "memory");
        __syncthreads();   // chunk-n data visible to all; buffer s^1 free; sw ready (n=0)

        // Prefetch chunk n+1 into the other buffer; flight hidden by compute.
        stage(c0 + CCHUNK, s ^ 1);
        asm volatile("cp.async.commit_group;" ::: "memory");

        #pragma unroll
        for (int cc = 0; cc < CCHUNK; cc++) {
            const int c = c0 + cc;
            #pragma unroll
            for (int i = 0; i < K_; i++) {
                const uint32_t* rowE = &sfe[s][cc][ty + i][xg * 4];
                const uint32_t* rowO = &sfo[s][cc][ty + i][xg * 4];
                const uint4 ea = *reinterpret_cast<const uint4*>(rowE);
                const uint2 eb = *reinterpret_cast<const uint2*>(rowE + 4);
                const uint4 oa = *reinterpret_cast<const uint4*>(rowO);
                const uint32_t ob = rowO[4];
                const uint32_t eu[6] = { ea.x, ea.y, ea.z, ea.w, eb.x, eb.y };
                const uint32_t ou[5] = { oa.x, oa.y, oa.z, oa.w, ob };

                #pragma unroll
                for (int j = 0; j < K_; j++) {
                    const uint4 wr =
                        *reinterpret_cast<const uint4*>(&sw[c][i * K_ + j][tg * 4]);
                    const uint32_t w2[4] = { wr.x, wr.y, wr.z, wr.w };
                    #pragma unroll
                    for (int p = 0; p < 4; p++) {
                        const uint32_t fp = (j & 1) ? ou[((j - 1) >> 1) + p]
                                                    : eu[(j >> 1) + p];
                        #pragma unroll
                        for (int oo = 0; oo < 4; oo++)
                            acc[oo][p] = __viaddmax_s16x2(fp, w2[oo], acc[oo][p]);
                    }
                }
            }
        }
    }

    // Epilogue: s16 -> fp32 * (1/2048), 2 float4 stores per o.
    float* ob2 = out + ((size_t)b * COUT + og * 8 + tg * 4) * (H_ * W_)
               + (size_t)(y0 + ty) * W_ + blockIdx.x * TILE_X + xg * 8;
    #pragma unroll
    for (int oo = 0; oo < 4; oo++) {
        float* op = ob2 + (size_t)oo * (H_ * W_);
        float v[8];
        #pragma unroll
        for (int p = 0; p < 4; p++) {
            const uint32_t a = acc[oo][p];
            v[2 * p]     = (float)((int)(int16_t)(a & 0xFFFF)) * INV_SCALE;
            v[2 * p + 1] = (float)((int)(int16_t)(a >> 16))    * INV_SCALE;
        }
        reinterpret_cast<float4*>(op)[0] = make_float4(v[0], v[1], v[2], v[3]);
        reinterpret_cast<float4*>(op)[1] = make_float4(v[4], v[5], v[6], v[7]);
    }
}

extern "C" void kernel_launch(void* const* d_in, const int* in_sizes, int n_in,
                              void* d_out, int out_size)
{
    const float* f = (const float*)d_in[0];
    const float* h = (const float*)d_in[1];
    float* out = (float*)d_out;

    prep_kernel<<<1024 + NW_BLOCKS, 256>>>(f, h);

    dim3 grid(W_ / TILE_X, H_ / TILE_Y, B_ * 4);  // (3, 6, 32)
    dilate2d_dpx_kernel<<<grid, 128>>>(out);
}

// round 10
// speedup vs baseline: 1.0306x; 1.0306x over previous
#include <cuda_runtime.h>
#include <cstdint>

#define B_    8
#define CIN   32
#define COUT  32
#define H_    96
#define W_    96
#define K_    5

#define TILE_X 32
#define TILE_Y 16
#define CCHUNK 8

#define SCALE_F   2048.0f
#define INV_SCALE (1.0f / 2048.0f)
#define NEG_PACK  0x8AD08AD0u   // (-30000, -30000) as s16x2
#define NEG_S16   ((int16_t)-30000)

#define NW_ELEMS  ((COUT / 8) * CIN * K_ * K_ * 8)   // 25600
#define NW_BLOCKS ((NW_ELEMS + 255) / 256)           // 100

// Padded s16x2 f, two phase-shifted images. Word w of a row:
//   E: covers gx = (2w-2, 2w-1)      O: covers gx = (2w-1, 2w)
// row r <-> gy = r-2. Borders = NEG. 6.55 MB each.
__device__ uint32_t g_fpadE[B_][CIN][100][64];
__device__ uint32_t g_fpadO[B_][CIN][100][64];
// Pre-transposed duplicated weights: [o_group of 8][c][ij][o_local], (w,w) s16x2.
__device__ uint32_t g_w[COUT / 8][CIN][K_ * K_][8];

__device__ __forceinline__ uint32_t pack_s16x2(int a, int b) {
    return (uint32_t)(uint16_t)a | ((uint32_t)(uint16_t)b << 16);
}

// ---- Fused prep: blocks 0..1023 convert f into BOTH phase images
//      (quarter-plane each); blocks 1024..1123 handle the 25600 weight entries.
__global__ __launch_bounds__(256) void prep_kernel(const float* __restrict__ f,
                                                   const float* __restrict__ h)
{
    const int bx  = blockIdx.x;
    const int tid = threadIdx.x;

    if (bx < 1024) {
        const int bc = bx >> 2;            // b*32 + c
        const int q  = bx & 3;             // quarter of the 6400-word plane
        const float* fp = f + (size_t)bc * (H_ * W_);
        uint32_t* dstE = &g_fpadE[0][0][0][0] + (size_t)bc * 6400;
        uint32_t* dstO = &g_fpadO[0][0][0][0] + (size_t)bc * 6400;
        #pragma unroll
        for (int k = 0; k < 7; k++) {
            const int wi = q * 1600 + tid + k * 256;
            if (wi < (q + 1) * 1600) {
                const int ry = wi >> 6;
                const int cw = wi & 63;
                uint32_t ve = NEG_PACK, vo = NEG_PACK;
                if (ry >= 2 && ry < 98) {
                    const float* row = fp + (ry - 2) * W_;
                    int lo, hi;
                    if (cw >= 1 && cw <= 48) {         // even: gx = 2cw-2, 2cw-1
                        lo = __float2int_rn(row[2 * cw - 2] * SCALE_F);
                        hi = __float2int_rn(row[2 * cw - 1] * SCALE_F);
                        ve = pack_s16x2(lo, hi);
                    }
                    lo = NEG_S16; hi = NEG_S16;        // odd: gx = 2cw-1, 2cw
                    if (cw >= 1 && cw <= 48) lo = __float2int_rn(row[2 * cw - 1] * SCALE_F);
                    if (cw < 48)             hi = __float2int_rn(row[2 * cw] * SCALE_F);
                    vo = pack_s16x2(lo, hi);
                }
                dstE[wi] = ve;
                dstO[wi] = vo;
            }
        }
    } else {
        const int idx = (bx - 1024) * 256 + tid;
        if (idx < NW_ELEMS) {
            const int og  = idx / (CIN * K_ * K_ * 8);
            const int rem = idx % (CIN * K_ * K_ * 8);
            const int c   = rem / (K_ * K_ * 8);
            const int r2  = rem % (K_ * K_ * 8);
            const int ij  = r2 >> 3;
            const int ol  = r2 & 7;
            const float wv =
                h[(size_t)(og * 8 + ol) * (CIN * K_ * K_) + c * (K_ * K_) + ij];
            const int wq = __float2int_rn(wv * SCALE_F);
            g_w[og][c][ij][ol] = pack_s16x2(wq, wq);
        }
    }
}

// ---- Main kernel ----
// 128 threads: xg = tid&3 (4 groups of 8 px), tg = (tid>>2)&1 (o half),
// ty = tid>>3 (16 rows). Each thread: 8 px x 4 o = 32 outputs.
// Block: 8 o x 16 y x 32 x. Grid (3, 6, B*4) = 576 (all co-resident, 4/SM).
__global__ __launch_bounds__(128) void dilate2d_dpx_kernel(float* __restrict__ out)
{
    __shared__ __align__(16) uint32_t sw[CIN][K_ * K_][8];          // 25.6 KB
    __shared__ __align__(16) uint32_t sfe[CCHUNK][TILE_Y + 4][20];  // 12.8 KB
    __shared__ __align__(16) uint32_t sfo[CCHUNK][TILE_Y + 4][20];  // 12.8 KB

    const int tid = threadIdx.x;
    const int xg  = tid & 3;
    const int tg  = (tid >> 2) & 1;
    const int ty  = tid >> 3;

    const int bz = blockIdx.z;
    const int b  = bz >> 2;
    const int og = bz & 3;
    const int x0h = blockIdx.x * (TILE_X / 2);
    const int y0  = blockIdx.y * TILE_Y;

    // Weights: vector copy of this o-group's pre-transposed block (1600 uint4).
    {
        const uint4* src = reinterpret_cast<const uint4*>(&g_w[og][0][0][0]);
        uint4* dst = reinterpret_cast<uint4*>(&sw[0][0][0]);
        #pragma unroll
        for (int k = 0; k < 12; k++)
            dst[tid + k * 128] = src[tid + k * 128];
        if (tid < 64) dst[tid + 1536] = src[tid + 1536];
    }

    uint32_t acc[4][4];
    #pragma unroll
    for (int oo = 0; oo < 4; oo++)
        #pragma unroll
        for (int p = 0; p < 4; p++)
            acc[oo][p] = NEG_PACK;

    #pragma unroll 1
    for (int n = 0; n < CIN / CCHUNK; n++) {     // 4 barrier rounds
        const int c0 = n * CCHUNK;
        if (n) __syncthreads();

        // Stage 8 channels x 20 rows x 2 images = 320 row-images as 160 items
        // of 18 words each (pure vector copies; no PRMT, no bounds checks).
        for (int it = tid; it < 2 * CCHUNK * (TILE_Y + 4); it += 128) {
            const int img = it & 1;
            const int rid = it >> 1;
            const int cc  = rid / (TILE_Y + 4);
            const int r   = rid % (TILE_Y + 4);
            const uint32_t* g = img ? &g_fpadO[b][c0 + cc][y0 + r][x0h]
                                    : &g_fpadE[b][c0 + cc][y0 + r][x0h];
            uint32_t* srow = img ? &sfo[cc][r][0] : &sfe[cc][r][0];
            #pragma unroll
            for (int k = 0; k < 4; k++)
                reinterpret_cast<uint4*>(srow)[k] =
                    reinterpret_cast<const uint4*>(g)[k];
            reinterpret_cast<uint2*>(srow)[8] =
                reinterpret_cast<const uint2*>(g)[8];
        }
        __syncthreads();   // round 0 also publishes sw

        #pragma unroll 1
        for (int half = 0; half < 2; half++) {
            #pragma unroll
            for (int cc4 = 0; cc4 < 4; cc4++) {
                const int cc = half * 4 + cc4;
                const int c  = c0 + cc;
                #pragma unroll
                for (int i = 0; i < K_; i++) {
                    const uint32_t* rowE = &sfe[cc][ty + i][xg * 4];
                    const uint32_t* rowO = &sfo[cc][ty + i][xg * 4];
                    const uint4 ea = *reinterpret_cast<const uint4*>(rowE);
                    const uint2 eb = *reinterpret_cast<const uint2*>(rowE + 4);
                    const uint4 oa = *reinterpret_cast<const uint4*>(rowO);
                    const uint32_t ob = rowO[4];
                    const uint32_t eu[6] = { ea.x, ea.y, ea.z, ea.w, eb.x, eb.y };
                    const uint32_t ou[5] = { oa.x, oa.y, oa.z, oa.w, ob };

                    #pragma unroll
                    for (int j = 0; j < K_; j++) {
                        const uint4 wr =
                            *reinterpret_cast<const uint4*>(&sw[c][i * K_ + j][tg * 4]);
                        const uint32_t w2[4] = { wr.x, wr.y, wr.z, wr.w };
                        #pragma unroll
                        for (int p = 0; p < 4; p++) {
                            const uint32_t fp = (j & 1) ? ou[((j - 1) >> 1) + p]
                                                        : eu[(j >> 1) + p];
                            #pragma unroll
                            for (int oo = 0; oo < 4; oo++)
                                acc[oo][p] = __viaddmax_s16x2(fp, w2[oo], acc[oo][p]);
                        }
                    }
                }
            }
        }
    }

    // Epilogue: s16 -> fp32 * (1/2048), 2 float4 stores per o.
    float* ob2 = out + ((size_t)b * COUT + og * 8 + tg * 4) * (H_ * W_)
               + (size_t)(y0 + ty) * W_ + blockIdx.x * TILE_X + xg * 8;
    #pragma unroll
    for (int oo = 0; oo < 4; oo++) {
        float* op = ob2 + (size_t)oo * (H_ * W_);
        float v[8];
        #pragma unroll
        for (int p = 0; p < 4; p++) {
            const uint32_t a = acc[oo][p];
            v[2 * p]     = (float)((int)(int16_t)(a & 0xFFFF)) * INV_SCALE;
            v[2 * p + 1] = (float)((int)(int16_t)(a >> 16))    * INV_SCALE;
        }
        reinterpret_cast<float4*>(op)[0] = make_float4(v[0], v[1], v[2], v[3]);
        reinterpret_cast<float4*>(op)[1] = make_float4(v[4], v[5], v[6], v[7]);
    }
}

extern "C" void kernel_launch(void* const* d_in, const int* in_sizes, int n_in,
                              void* d_out, int out_size)
{
    const float* f = (const float*)d_in[0];
    const float* h = (const float*)d_in[1];
    float* out = (float*)d_out;

    prep_kernel<<<1024 + NW_BLOCKS, 256>>>(f, h);

    dim3 grid(W_ / TILE_X, H_ / TILE_Y, B_ * 4);  // (3, 6, 32)
    dilate2d_dpx_kernel<<<grid, 128>>>(out);
}